// round 3
// baseline (speedup 1.0000x reference)
#include <cuda_runtime.h>
#include <math.h>

// Problem dims (fixed by the reference)
#define NB 256            // batch
#define NT 128            // seq len
#define ND 512            // embed dim
#define NS 256            // shrink dim
#define NM (NB*NT)        // 32768 flattened (t,b) rows

#define SGRID 128         // persistent step kernel CTAs (16 m-blocks x 8 n-blocks)
// Ws[512][64] + hs[16][512] + red[128][8]
#define STEP_SMEM ((512*64 + 16*512 + 128*8) * 4)

// ---------------------------------------------------------------------------
// Scratch (device globals; no runtime allocation allowed)
// ---------------------------------------------------------------------------
__device__ float g_C1[(size_t)NM * NS];     // relu(E @ W_inp^T + b_inp)
__device__ float g_L [(size_t)NM * ND];     // relu(C1 @ W_mid^T + b_mid)  [t][b][512]
__device__ float g_h [2][(size_t)NB * ND];  // recurrent state ping-pong
__device__ unsigned g_flag[SGRID];          // per-CTA step counters (barrier)

// ---------------------------------------------------------------------------
// FF GEMM: 128x128 tile, BK=8, 256 threads, 8x8 microtile (unchanged from R2)
// ---------------------------------------------------------------------------
__global__ __launch_bounds__(256) void gemm1_kernel(
    const int*   __restrict__ x,
    const float* __restrict__ emb,
    const float* __restrict__ W,     // [NS][ND]
    const float* __restrict__ bias)  // [NS]
{
    __shared__ float As[8][132];
    __shared__ float Bs[8][132];

    const int tid = threadIdx.x;
    const int m0  = blockIdx.y * 128;
    const int n0  = blockIdx.x * 128;

    const int ar = tid >> 1;
    const int kq = tid & 1;

    const int m   = m0 + ar;
    const int b   = m & (NB - 1);
    const int t   = m >> 8;
    const int tok = x[b * NT + t];
    const bool az = (tok == 0);
    const float* arow = emb + (size_t)tok * ND;
    const float* brow = W   + (size_t)(n0 + ar) * ND;

    const int tm = tid >> 4;
    const int tn = tid & 15;

    float acc[8][8] = {};

    for (int k0 = 0; k0 < ND; k0 += 8) {
        float4 av = az ? make_float4(0.f,0.f,0.f,0.f) : *(const float4*)&arow[k0 + kq*4];
        float4 bv = *(const float4*)&brow[k0 + kq*4];
        As[kq*4+0][ar]=av.x; As[kq*4+1][ar]=av.y; As[kq*4+2][ar]=av.z; As[kq*4+3][ar]=av.w;
        Bs[kq*4+0][ar]=bv.x; Bs[kq*4+1][ar]=bv.y; Bs[kq*4+2][ar]=bv.z; Bs[kq*4+3][ar]=bv.w;
        __syncthreads();
#pragma unroll
        for (int kk = 0; kk < 8; kk++) {
            float a[8], bb[8];
            *(float4*)&a[0]  = *(const float4*)&As[kk][tm*8];
            *(float4*)&a[4]  = *(const float4*)&As[kk][tm*8+4];
            *(float4*)&bb[0] = *(const float4*)&Bs[kk][tn*8];
            *(float4*)&bb[4] = *(const float4*)&Bs[kk][tn*8+4];
#pragma unroll
            for (int i=0;i<8;i++)
#pragma unroll
                for (int j=0;j<8;j++) acc[i][j] += a[i]*bb[j];
        }
        __syncthreads();
    }

    float4 c0 = *(const float4*)&bias[n0+tn*8];
    float4 c1 = *(const float4*)&bias[n0+tn*8+4];
    float bias8[8] = {c0.x,c0.y,c0.z,c0.w,c1.x,c1.y,c1.z,c1.w};
#pragma unroll
    for (int i=0;i<8;i++) {
        const int mr = m0 + tm*8 + i;
        float o[8];
#pragma unroll
        for (int j=0;j<8;j++) o[j] = fmaxf(acc[i][j] + bias8[j], 0.f);
        *(float4*)&g_C1[(size_t)mr*NS + n0 + tn*8    ] = *(float4*)&o[0];
        *(float4*)&g_C1[(size_t)mr*NS + n0 + tn*8 + 4] = *(float4*)&o[4];
    }
}

__global__ __launch_bounds__(256) void gemm2_kernel(
    const float* __restrict__ W,     // [ND][NS]
    const float* __restrict__ bias)  // [ND]
{
    __shared__ float As[8][132];
    __shared__ float Bs[8][132];

    const int tid = threadIdx.x;
    const int m0  = blockIdx.y * 128;
    const int n0  = blockIdx.x * 128;

    const int ar = tid >> 1;
    const int kq = tid & 1;

    const float* arow = g_C1 + (size_t)(m0 + ar) * NS;
    const float* brow = W    + (size_t)(n0 + ar) * NS;

    const int tm = tid >> 4;
    const int tn = tid & 15;

    float acc[8][8] = {};

    for (int k0 = 0; k0 < NS; k0 += 8) {
        float4 av = *(const float4*)&arow[k0 + kq*4];
        float4 bv = *(const float4*)&brow[k0 + kq*4];
        As[kq*4+0][ar]=av.x; As[kq*4+1][ar]=av.y; As[kq*4+2][ar]=av.z; As[kq*4+3][ar]=av.w;
        Bs[kq*4+0][ar]=bv.x; Bs[kq*4+1][ar]=bv.y; Bs[kq*4+2][ar]=bv.z; Bs[kq*4+3][ar]=bv.w;
        __syncthreads();
#pragma unroll
        for (int kk = 0; kk < 8; kk++) {
            float a[8], bb[8];
            *(float4*)&a[0]  = *(const float4*)&As[kk][tm*8];
            *(float4*)&a[4]  = *(const float4*)&As[kk][tm*8+4];
            *(float4*)&bb[0] = *(const float4*)&Bs[kk][tn*8];
            *(float4*)&bb[4] = *(const float4*)&Bs[kk][tn*8+4];
#pragma unroll
            for (int i=0;i<8;i++)
#pragma unroll
                for (int j=0;j<8;j++) acc[i][j] += a[i]*bb[j];
        }
        __syncthreads();
    }

    float4 c0 = *(const float4*)&bias[n0+tn*8];
    float4 c1 = *(const float4*)&bias[n0+tn*8+4];
    float bias8[8] = {c0.x,c0.y,c0.z,c0.w,c1.x,c1.y,c1.z,c1.w};
#pragma unroll
    for (int i=0;i<8;i++) {
        const int mr = m0 + tm*8 + i;
        float o[8];
#pragma unroll
        for (int j=0;j<8;j++) o[j] = fmaxf(acc[i][j] + bias8[j], 0.f);
        *(float4*)&g_L[(size_t)mr*ND + n0 + tn*8    ] = *(float4*)&o[0];
        *(float4*)&g_L[(size_t)mr*ND + n0 + tn*8 + 4] = *(float4*)&o[4];
    }
}

// ---------------------------------------------------------------------------
// Barrier flag reset (graph replays reuse state; must run before step_persist)
// ---------------------------------------------------------------------------
__global__ void init_bar_kernel()
{
    if (threadIdx.x < SGRID) g_flag[threadIdx.x] = 0u;
}

// ---------------------------------------------------------------------------
// Persistent recurrent kernel. 128 CTAs x 256 threads.
// CTA tile 16(M) x 64(N); W_hid slice [64 n][512 k] cached k-major in smem.
// Split-K: warps 0-3 do k[0,256), warps 4-7 k[256,512); smem reduction.
// Thread microtile 4m x 2n; a = float4 broadcast, b = float2 conflict-free.
// Inter-step sync: per-CTA flag array, parallel polling.
// ---------------------------------------------------------------------------
__global__ __launch_bounds__(256, 1) void step_persist(
    const float* __restrict__ Wh,     // [ND][ND]
    const float* __restrict__ bhid)   // [ND]
{
    extern __shared__ float sm[];
    float* Ws  = sm;                    // [512][64] k-major: Ws[k*64+nl] = Wh[n0+nl][k]
    float* hs  = sm + 512*64;           // [16][512]
    float* red = hs + 16*512;           // [128][8] split-K partials

    const int tid  = threadIdx.x;
    const int bx   = blockIdx.x;
    const int n0   = (bx & 7) * 64;
    const int m0   = (bx >> 3) * 16;
    const int half = tid >> 7;          // k-half: 0 or 1
    const int lt   = tid & 127;
    const int tm   = lt >> 5;           // 0..3
    const int tn   = lt & 31;           // 0..31
    const int kbeg = half * 256;

    // Cache W slice once (transpose to k-major; smem stores conflict-free:
    // lanes share kc, consecutive nl)
#pragma unroll 4
    for (int i = 0; i < 32; i++) {
        const int idx = tid + i*256;    // 0..8191
        const int nl  = idx & 63;
        const int kc  = idx >> 6;       // 0..127 (float4 within k row)
        float4 w = *(const float4*)&Wh[(size_t)(n0+nl)*ND + kc*4];
        Ws[(kc*4+0)*64 + nl] = w.x;
        Ws[(kc*4+1)*64 + nl] = w.y;
        Ws[(kc*4+2)*64 + nl] = w.z;
        Ws[(kc*4+3)*64 + nl] = w.w;
    }
    const float bb0 = bhid[n0 + tn*2];
    const float bb1 = bhid[n0 + tn*2 + 1];
    __syncthreads();

    for (int t = 0; t < NT; t++) {
        const float* __restrict__ Lt   = g_L + (size_t)t * NB * ND;
        float*       __restrict__ hout = g_h[(t+1) & 1];

        // prefetch Lt microtile (immutable; L1-cacheable) to hide L2 latency
        float2 l[4];
        if (half == 0) {
#pragma unroll
            for (int i = 0; i < 4; i++)
                l[i] = __ldg((const float2*)&Lt[(size_t)(m0 + tm*4 + i)*ND + n0 + tn*2]);
        }

        float acc[4][2] = {};
        if (t > 0) {
            const float* __restrict__ hin = g_h[t & 1];
            // stage h tile (bypass L1: written by other SMs last step)
#pragma unroll
            for (int i = 0; i < 8; i++) {
                const int idx = tid + i*256;   // 0..2047 float4 slots
                const int r   = idx >> 7;
                const int kc  = idx & 127;
                float4 v = __ldcg((const float4*)&hin[(size_t)(m0+r)*ND + kc*4]);
                *(float4*)&hs[r*512 + kc*4] = v;
            }
            __syncthreads();

            const float* a0p = &hs[(tm*4+0)*512];
            const float* a1p = &hs[(tm*4+1)*512];
            const float* a2p = &hs[(tm*4+2)*512];
            const float* a3p = &hs[(tm*4+3)*512];
            const float* wp  = &Ws[tn*2];

            for (int k = kbeg; k < kbeg + 256; k += 4) {
                float4 a0 = *(const float4*)&a0p[k];
                float4 a1 = *(const float4*)&a1p[k];
                float4 a2 = *(const float4*)&a2p[k];
                float4 a3 = *(const float4*)&a3p[k];
                float2 b0 = *(const float2*)&wp[(k+0)*64];
                float2 b1 = *(const float2*)&wp[(k+1)*64];
                float2 b2 = *(const float2*)&wp[(k+2)*64];
                float2 b3 = *(const float2*)&wp[(k+3)*64];

                acc[0][0] += a0.x*b0.x; acc[0][1] += a0.x*b0.y;
                acc[1][0] += a1.x*b0.x; acc[1][1] += a1.x*b0.y;
                acc[2][0] += a2.x*b0.x; acc[2][1] += a2.x*b0.y;
                acc[3][0] += a3.x*b0.x; acc[3][1] += a3.x*b0.y;

                acc[0][0] += a0.y*b1.x; acc[0][1] += a0.y*b1.y;
                acc[1][0] += a1.y*b1.x; acc[1][1] += a1.y*b1.y;
                acc[2][0] += a2.y*b1.x; acc[2][1] += a2.y*b1.y;
                acc[3][0] += a3.y*b1.x; acc[3][1] += a3.y*b1.y;

                acc[0][0] += a0.z*b2.x; acc[0][1] += a0.z*b2.y;
                acc[1][0] += a1.z*b2.x; acc[1][1] += a1.z*b2.y;
                acc[2][0] += a2.z*b2.x; acc[2][1] += a2.z*b2.y;
                acc[3][0] += a3.z*b2.x; acc[3][1] += a3.z*b2.y;

                acc[0][0] += a0.w*b3.x; acc[0][1] += a0.w*b3.y;
                acc[1][0] += a1.w*b3.x; acc[1][1] += a1.w*b3.y;
                acc[2][0] += a2.w*b3.x; acc[2][1] += a2.w*b3.y;
                acc[3][0] += a3.w*b3.x; acc[3][1] += a3.w*b3.y;
            }
        }

        // split-K reduce: half 1 publishes, half 0 combines + epilogue
        __syncthreads();           // hs fully consumed; red safe to write
        if (half == 1) {
            float* rp = &red[lt*8];
            *(float4*)&rp[0] = make_float4(acc[0][0], acc[0][1], acc[1][0], acc[1][1]);
            *(float4*)&rp[4] = make_float4(acc[2][0], acc[2][1], acc[3][0], acc[3][1]);
        }
        __syncthreads();
        if (half == 0) {
            const float* rp = &red[lt*8];
            float4 r0 = *(const float4*)&rp[0];
            float4 r1 = *(const float4*)&rp[4];
            acc[0][0] += r0.x; acc[0][1] += r0.y;
            acc[1][0] += r0.z; acc[1][1] += r0.w;
            acc[2][0] += r1.x; acc[2][1] += r1.y;
            acc[3][0] += r1.z; acc[3][1] += r1.w;
#pragma unroll
            for (int i = 0; i < 4; i++) {
                const int mr = m0 + tm*4 + i;
                float2 o;
                o.x = tanhf(acc[i][0] + l[i].x + bb0);
                o.y = tanhf(acc[i][1] + l[i].y + bb1);
                *(float2*)&hout[(size_t)mr*ND + n0 + tn*2] = o;
            }
            __threadfence();       // make this thread's h stores globally visible
        }
        __syncthreads();

        // chip-wide barrier: publish own flag, poll all 128 in parallel
        if (tid == 0) ((volatile unsigned*)g_flag)[bx] = (unsigned)(t + 1);
        if (tid < SGRID) {
            while (((volatile unsigned*)g_flag)[tid] < (unsigned)(t + 1)) {
                __nanosleep(32);
            }
        }
        __syncthreads();
    }
}

// ---------------------------------------------------------------------------
// Row L2-normalize final h (g_h[0] after 128 steps)
// ---------------------------------------------------------------------------
__global__ __launch_bounds__(128) void norm_kernel(float* __restrict__ out)
{
    __shared__ float red[4];
    const int row = blockIdx.x;
    const int tid = threadIdx.x;

    const float* h = g_h[0] + (size_t)row * ND;
    float4 v = *(const float4*)&h[tid * 4];
    float s = v.x*v.x + v.y*v.y + v.z*v.z + v.w*v.w;
#pragma unroll
    for (int o = 16; o; o >>= 1) s += __shfl_xor_sync(0xFFFFFFFFu, s, o);
    if ((tid & 31) == 0) red[tid >> 5] = s;
    __syncthreads();
    const float tot = red[0] + red[1] + red[2] + red[3];
    const float inv = 1.f / fmaxf(sqrtf(tot), 1e-12f);
    float4 o4 = make_float4(v.x*inv, v.y*inv, v.z*inv, v.w*inv);
    *(float4*)&out[(size_t)row * ND + tid * 4] = o4;
}

// ---------------------------------------------------------------------------
// Launch
// ---------------------------------------------------------------------------
extern "C" void kernel_launch(void* const* d_in, const int* in_sizes, int n_in,
                              void* d_out, int out_size)
{
    const int*   x     = (const int*)  d_in[0];
    const float* emb   = (const float*)d_in[1];
    const float* W_inp = (const float*)d_in[2];
    const float* b_inp = (const float*)d_in[3];
    const float* W_mid = (const float*)d_in[4];
    const float* b_mid = (const float*)d_in[5];
    const float* W_hid = (const float*)d_in[6];
    const float* b_hid = (const float*)d_in[7];
    float* out = (float*)d_out;

    cudaFuncSetAttribute(step_persist, cudaFuncAttributeMaxDynamicSharedMemorySize, STEP_SMEM);

    gemm1_kernel<<<dim3(NS/128, NM/128), 256>>>(x, emb, W_inp, b_inp);
    gemm2_kernel<<<dim3(ND/128, NM/128), 256>>>(W_mid, b_mid);

    init_bar_kernel<<<1, SGRID>>>();
    step_persist<<<SGRID, 256, STEP_SMEM>>>(W_hid, b_hid);

    norm_kernel<<<NB, 128>>>(out);
}

// round 4
// speedup vs baseline: 1.4575x; 1.4575x over previous
#include <cuda_runtime.h>
#include <math.h>
#include <stdint.h>

// Problem dims (fixed by the reference)
#define NB 256            // batch
#define NT 128            // seq len
#define ND 512            // embed dim
#define NS 256            // shrink dim
#define NM (NB*NT)        // 32768 flattened (t,b) rows

#define SGRID 128         // persistent step kernel CTAs
#define STEP_SMEM ((512*64 + 16*512) * 4)   // Ws[512][64] + hs[16][512] floats

// ---------------------------------------------------------------------------
// Scratch (device globals; no runtime allocation allowed)
// ---------------------------------------------------------------------------
__device__ float g_C1[(size_t)NM * NS];     // relu(E @ W_inp^T + b_inp)
__device__ float g_L [(size_t)NM * ND];     // relu(C1 @ W_mid^T + b_mid)  [t][b][512]
__device__ float g_h [2][(size_t)NB * ND];  // recurrent state ping-pong

__device__ unsigned          g_arrive;      // grid barrier arrivals (cumulative)
__device__ volatile unsigned g_gen;         // grid barrier generation

// ---------------------------------------------------------------------------
// tf32 helpers
// ---------------------------------------------------------------------------
__device__ __forceinline__ uint32_t f2tf(float f)
{
    uint32_t u;
    asm("cvt.rna.tf32.f32 %0, %1;" : "=r"(u) : "f"(f));
    return u;
}

__device__ __forceinline__ void mma_tf32(float d[4], const uint32_t a[4], const uint32_t b[2])
{
    asm volatile(
        "mma.sync.aligned.m16n8k8.row.col.f32.tf32.tf32.f32 "
        "{%0,%1,%2,%3}, {%4,%5,%6,%7}, {%8,%9}, {%0,%1,%2,%3};"
        : "+f"(d[0]), "+f"(d[1]), "+f"(d[2]), "+f"(d[3])
        : "r"(a[0]), "r"(a[1]), "r"(a[2]), "r"(a[3]), "r"(b[0]), "r"(b[1]));
}

// ---------------------------------------------------------------------------
// FF GEMMs with tf32 tensor cores.
// CTA 128(M)x128(N), BK=32, 256 threads = 8 warps in 2(M)x4(N) grid;
// warp tile 64x32 = 4(mf) x 4(nf) m16n8k8 fragments.
// Smem rows padded to 36 words -> frag LDS conflict-free ((4r+c) mod 32).
// ---------------------------------------------------------------------------

// GEMM1: C1[m][n] = relu( sum_k E[m][k] * W_inp[n][k] + b_inp[n] ), K=512, N=256
//   E[m][k] = (tok==0) ? 0 : emb[tok*ND+k],  tok = x[b*NT+t], m = t*NB+b
__global__ __launch_bounds__(256) void gemm1_kernel(
    const int*   __restrict__ x,
    const float* __restrict__ emb,
    const float* __restrict__ W,     // [NS][ND]
    const float* __restrict__ bias)  // [NS]
{
    __shared__ __align__(16) uint32_t As[128][36];
    __shared__ __align__(16) uint32_t Bs[128][36];

    const int tid  = threadIdx.x;
    const int warp = tid >> 5;
    const int lane = tid & 31;
    const int m0c  = blockIdx.y * 128;
    const int n0c  = blockIdx.x * 128;

    // load roles: 2 threads per row, each 16 consecutive k (4 float4)
    const int row = tid >> 1;
    const int kq  = tid & 1;

    const int m   = m0c + row;
    const int bb_ = m & (NB - 1);
    const int tt_ = m >> 8;
    const int tok = x[bb_ * NT + tt_];
    const bool az = (tok == 0);
    const float* arow = emb + (size_t)tok * ND;
    const float* brow = W   + (size_t)(n0c + row) * ND;

    // mma roles
    const int wm = (warp & 1) * 64;
    const int wn = (warp >> 1) * 32;
    const int ly = lane >> 2;
    const int lx = lane & 3;

    float acc[4][4][4] = {};

    float4 pa[4], pb[4];
#pragma unroll
    for (int q = 0; q < 4; q++) {
        pa[q] = az ? make_float4(0.f,0.f,0.f,0.f) : *(const float4*)&arow[kq*16 + q*4];
        pb[q] = *(const float4*)&brow[kq*16 + q*4];
    }

    for (int k0 = 0; k0 < ND; k0 += 32) {
#pragma unroll
        for (int q = 0; q < 4; q++) {
            const int c = kq*16 + q*4;
            *(uint4*)&As[row][c] = make_uint4(f2tf(pa[q].x), f2tf(pa[q].y), f2tf(pa[q].z), f2tf(pa[q].w));
            *(uint4*)&Bs[row][c] = make_uint4(f2tf(pb[q].x), f2tf(pb[q].y), f2tf(pb[q].z), f2tf(pb[q].w));
        }
        __syncthreads();
        if (k0 + 32 < ND) {
#pragma unroll
            for (int q = 0; q < 4; q++) {
                pa[q] = az ? make_float4(0.f,0.f,0.f,0.f) : *(const float4*)&arow[k0+32 + kq*16 + q*4];
                pb[q] = *(const float4*)&brow[k0+32 + kq*16 + q*4];
            }
        }
#pragma unroll
        for (int kk = 0; kk < 4; kk++) {
            const int kb = kk * 8;
            uint32_t af[4][4], bf[4][2];
#pragma unroll
            for (int mf = 0; mf < 4; mf++) {
                const int rb = wm + mf*16 + ly;
                af[mf][0] = As[rb    ][kb + lx];
                af[mf][1] = As[rb + 8][kb + lx];
                af[mf][2] = As[rb    ][kb + lx + 4];
                af[mf][3] = As[rb + 8][kb + lx + 4];
            }
#pragma unroll
            for (int nf = 0; nf < 4; nf++) {
                const int nb = wn + nf*8 + ly;
                bf[nf][0] = Bs[nb][kb + lx];
                bf[nf][1] = Bs[nb][kb + lx + 4];
            }
#pragma unroll
            for (int mf = 0; mf < 4; mf++)
#pragma unroll
                for (int nf = 0; nf < 4; nf++)
                    mma_tf32(acc[mf][nf], af[mf], bf[nf]);
        }
        __syncthreads();
    }

    // epilogue: bias + relu
#pragma unroll
    for (int nf = 0; nf < 4; nf++) {
        const int gn = n0c + wn + nf*8 + lx*2;
        const float2 bv = *(const float2*)&bias[gn];
#pragma unroll
        for (int mf = 0; mf < 4; mf++) {
            const int gm0 = m0c + wm + mf*16 + ly;
            float2 o0, o1;
            o0.x = fmaxf(acc[mf][nf][0] + bv.x, 0.f);
            o0.y = fmaxf(acc[mf][nf][1] + bv.y, 0.f);
            o1.x = fmaxf(acc[mf][nf][2] + bv.x, 0.f);
            o1.y = fmaxf(acc[mf][nf][3] + bv.y, 0.f);
            *(float2*)&g_C1[(size_t)gm0*NS + gn]       = o0;
            *(float2*)&g_C1[(size_t)(gm0+8)*NS + gn]   = o1;
        }
    }
}

// GEMM2: L[m][n] = relu( sum_k C1[m][k] * W_mid[n][k] + b_mid[n] ), K=256, N=512
__global__ __launch_bounds__(256) void gemm2_kernel(
    const float* __restrict__ W,     // [ND][NS]
    const float* __restrict__ bias)  // [ND]
{
    __shared__ __align__(16) uint32_t As[128][36];
    __shared__ __align__(16) uint32_t Bs[128][36];

    const int tid  = threadIdx.x;
    const int warp = tid >> 5;
    const int lane = tid & 31;
    const int m0c  = blockIdx.y * 128;
    const int n0c  = blockIdx.x * 128;

    const int row = tid >> 1;
    const int kq  = tid & 1;

    const float* arow = g_C1 + (size_t)(m0c + row) * NS;
    const float* brow = W    + (size_t)(n0c + row) * NS;

    const int wm = (warp & 1) * 64;
    const int wn = (warp >> 1) * 32;
    const int ly = lane >> 2;
    const int lx = lane & 3;

    float acc[4][4][4] = {};

    float4 pa[4], pb[4];
#pragma unroll
    for (int q = 0; q < 4; q++) {
        pa[q] = *(const float4*)&arow[kq*16 + q*4];
        pb[q] = *(const float4*)&brow[kq*16 + q*4];
    }

    for (int k0 = 0; k0 < NS; k0 += 32) {
#pragma unroll
        for (int q = 0; q < 4; q++) {
            const int c = kq*16 + q*4;
            *(uint4*)&As[row][c] = make_uint4(f2tf(pa[q].x), f2tf(pa[q].y), f2tf(pa[q].z), f2tf(pa[q].w));
            *(uint4*)&Bs[row][c] = make_uint4(f2tf(pb[q].x), f2tf(pb[q].y), f2tf(pb[q].z), f2tf(pb[q].w));
        }
        __syncthreads();
        if (k0 + 32 < NS) {
#pragma unroll
            for (int q = 0; q < 4; q++) {
                pa[q] = *(const float4*)&arow[k0+32 + kq*16 + q*4];
                pb[q] = *(const float4*)&brow[k0+32 + kq*16 + q*4];
            }
        }
#pragma unroll
        for (int kk = 0; kk < 4; kk++) {
            const int kb = kk * 8;
            uint32_t af[4][4], bf[4][2];
#pragma unroll
            for (int mf = 0; mf < 4; mf++) {
                const int rb = wm + mf*16 + ly;
                af[mf][0] = As[rb    ][kb + lx];
                af[mf][1] = As[rb + 8][kb + lx];
                af[mf][2] = As[rb    ][kb + lx + 4];
                af[mf][3] = As[rb + 8][kb + lx + 4];
            }
#pragma unroll
            for (int nf = 0; nf < 4; nf++) {
                const int nb = wn + nf*8 + ly;
                bf[nf][0] = Bs[nb][kb + lx];
                bf[nf][1] = Bs[nb][kb + lx + 4];
            }
#pragma unroll
            for (int mf = 0; mf < 4; mf++)
#pragma unroll
                for (int nf = 0; nf < 4; nf++)
                    mma_tf32(acc[mf][nf], af[mf], bf[nf]);
        }
        __syncthreads();
    }

#pragma unroll
    for (int nf = 0; nf < 4; nf++) {
        const int gn = n0c + wn + nf*8 + lx*2;
        const float2 bv = *(const float2*)&bias[gn];
#pragma unroll
        for (int mf = 0; mf < 4; mf++) {
            const int gm0 = m0c + wm + mf*16 + ly;
            float2 o0, o1;
            o0.x = fmaxf(acc[mf][nf][0] + bv.x, 0.f);
            o0.y = fmaxf(acc[mf][nf][1] + bv.y, 0.f);
            o1.x = fmaxf(acc[mf][nf][2] + bv.x, 0.f);
            o1.y = fmaxf(acc[mf][nf][3] + bv.y, 0.f);
            *(float2*)&g_L[(size_t)gm0*ND + gn]       = o0;
            *(float2*)&g_L[(size_t)(gm0+8)*ND + gn]   = o1;
        }
    }
}

// ---------------------------------------------------------------------------
// Barrier state reset (must run before every step_persist launch)
// ---------------------------------------------------------------------------
__global__ void init_bar_kernel()
{
    if (threadIdx.x == 0) { g_arrive = 0; g_gen = 0; }
}

// ---------------------------------------------------------------------------
// Persistent recurrent kernel (R2 configuration — measured best).
// 128 CTAs x 128 threads. CTA tile 16(M)x64(N); W_hid slice cached k-major
// in smem once. Per step: stage h via __ldcg, fp32 GEMM, +L_t+bias, tanh,
// store, atomic grid barrier.
// ---------------------------------------------------------------------------
__global__ __launch_bounds__(128, 1) void step_persist(
    const float* __restrict__ Wh,     // [ND][ND]
    const float* __restrict__ bhid)   // [ND]
{
    extern __shared__ float sm[];
    float* Ws = sm;                  // [512][64] k-major: Ws[k*64 + nl] = Wh[n0+nl][k]
    float* hs = sm + 512*64;         // [16][512]

    const int tid = threadIdx.x;
    const int bx  = blockIdx.x;
    const int n0  = (bx & 7) * 64;
    const int m0  = (bx >> 3) * 16;
    const int tm  = tid >> 5;        // 0..3
    const int tn  = tid & 31;        // 0..31

    // Cache W slice once (transpose to k-major)
#pragma unroll 4
    for (int i = 0; i < 64; i++) {
        const int idx = tid + i*128;
        const int nl  = idx >> 7;
        const int kc  = idx & 127;
        float4 w = *(const float4*)&Wh[(size_t)(n0+nl)*ND + kc*4];
        Ws[(kc*4+0)*64 + nl] = w.x;
        Ws[(kc*4+1)*64 + nl] = w.y;
        Ws[(kc*4+2)*64 + nl] = w.z;
        Ws[(kc*4+3)*64 + nl] = w.w;
    }
    const float bb0 = bhid[n0 + tn*2];
    const float bb1 = bhid[n0 + tn*2 + 1];
    __syncthreads();

    for (int t = 0; t < NT; t++) {
        const float* __restrict__ Lt   = g_L + (size_t)t * NB * ND;
        float*       __restrict__ hout = g_h[(t+1) & 1];

        float acc[4][2] = {};
        if (t > 0) {
            const float* __restrict__ hin = g_h[t & 1];
#pragma unroll 4
            for (int i = 0; i < 16; i++) {
                const int idx = tid + i*128;
                const int r   = idx >> 7;
                const int kc  = idx & 127;
                float4 v = __ldcg((const float4*)&hin[(size_t)(m0+r)*ND + kc*4]);
                *(float4*)&hs[r*512 + kc*4] = v;
            }
            __syncthreads();

            const float* a0 = &hs[(tm*4+0)*512];
            const float* a1 = &hs[(tm*4+1)*512];
            const float* a2 = &hs[(tm*4+2)*512];
            const float* a3 = &hs[(tm*4+3)*512];
            const float* wp = &Ws[tn*2];
#pragma unroll 8
            for (int k = 0; k < 512; k++) {
                const float b0 = wp[k*64];
                const float b1 = wp[k*64 + 1];
                const float x0 = a0[k], x1 = a1[k], x2 = a2[k], x3 = a3[k];
                acc[0][0] += x0*b0; acc[0][1] += x0*b1;
                acc[1][0] += x1*b0; acc[1][1] += x1*b1;
                acc[2][0] += x2*b0; acc[2][1] += x2*b1;
                acc[3][0] += x3*b0; acc[3][1] += x3*b1;
            }
        }

#pragma unroll
        for (int i = 0; i < 4; i++) {
            const int mr = m0 + tm*4 + i;
            const float2 l2 = *(const float2*)&Lt[(size_t)mr*ND + n0 + tn*2];
            float2 o;
            o.x = tanhf(acc[i][0] + l2.x + bb0);
            o.y = tanhf(acc[i][1] + l2.y + bb1);
            *(float2*)&hout[(size_t)mr*ND + n0 + tn*2] = o;
        }

        __syncthreads();
        if (tid == 0) {
            __threadfence();
            const unsigned bn = (unsigned)(t + 1);
            const unsigned v = atomicAdd(&g_arrive, 1u) + 1u;
            if (v == bn * SGRID) {
                g_gen = bn;
            } else {
                while (*(volatile unsigned*)&g_gen < bn) { }
            }
        }
        __syncthreads();
    }
}

// ---------------------------------------------------------------------------
// Row L2-normalize final h (g_h[0] after 128 steps)
// ---------------------------------------------------------------------------
__global__ __launch_bounds__(128) void norm_kernel(float* __restrict__ out)
{
    __shared__ float red[4];
    const int row = blockIdx.x;
    const int tid = threadIdx.x;

    const float* h = g_h[0] + (size_t)row * ND;
    float4 v = *(const float4*)&h[tid * 4];
    float s = v.x*v.x + v.y*v.y + v.z*v.z + v.w*v.w;
#pragma unroll
    for (int o = 16; o; o >>= 1) s += __shfl_xor_sync(0xFFFFFFFFu, s, o);
    if ((tid & 31) == 0) red[tid >> 5] = s;
    __syncthreads();
    const float tot = red[0] + red[1] + red[2] + red[3];
    const float inv = 1.f / fmaxf(sqrtf(tot), 1e-12f);
    float4 o4 = make_float4(v.x*inv, v.y*inv, v.z*inv, v.w*inv);
    *(float4*)&out[(size_t)row * ND + tid * 4] = o4;
}

// ---------------------------------------------------------------------------
// Launch
// ---------------------------------------------------------------------------
extern "C" void kernel_launch(void* const* d_in, const int* in_sizes, int n_in,
                              void* d_out, int out_size)
{
    const int*   x     = (const int*)  d_in[0];
    const float* emb   = (const float*)d_in[1];
    const float* W_inp = (const float*)d_in[2];
    const float* b_inp = (const float*)d_in[3];
    const float* W_mid = (const float*)d_in[4];
    const float* b_mid = (const float*)d_in[5];
    const float* W_hid = (const float*)d_in[6];
    const float* b_hid = (const float*)d_in[7];
    float* out = (float*)d_out;

    cudaFuncSetAttribute(step_persist, cudaFuncAttributeMaxDynamicSharedMemorySize, STEP_SMEM);

    // Feed-forward part for ALL timesteps (tensor cores, tf32)
    gemm1_kernel<<<dim3(NS/128, NM/128), 256>>>(x, emb, W_inp, b_inp);
    gemm2_kernel<<<dim3(ND/128, NM/128), 256>>>(W_mid, b_mid);

    // Recurrence: one persistent kernel with internal grid barriers
    init_bar_kernel<<<1, 32>>>();
    step_persist<<<SGRID, 128, STEP_SMEM>>>(W_hid, b_hid);

    norm_kernel<<<NB, 128>>>(out);
}

// round 5
// speedup vs baseline: 2.0685x; 1.4192x over previous
#include <cuda_runtime.h>
#include <math.h>
#include <stdint.h>

// Problem dims (fixed by the reference)
#define NB 256            // batch
#define NT 128            // seq len
#define ND 512            // embed dim
#define NS 256            // shrink dim
#define NM (NB*NT)        // 32768 flattened (t,b) rows

#define SGRID 128         // step kernel CTAs: 8 m-blocks x 16 n-blocks
#define SROW 516          // padded smem row (512 + 4) -> conflict-free frags
// Ws_hi[32][516] + Ws_lo[32][516] + hs[32][516] floats
#define STEP_SMEM (3 * 32 * SROW * 4)

// ---------------------------------------------------------------------------
// Scratch (device globals; no runtime allocation allowed)
// ---------------------------------------------------------------------------
__device__ float g_C1[(size_t)NM * NS];     // relu(E @ W_inp^T + b_inp)
__device__ float g_L [(size_t)NM * ND];     // relu(C1 @ W_mid^T + b_mid)  [t][b][512]
__device__ float g_h [2][(size_t)NB * ND];  // recurrent state ping-pong
__device__ unsigned g_flag[8];              // per-m-block step counters

// ---------------------------------------------------------------------------
// tf32 helpers
// ---------------------------------------------------------------------------
__device__ __forceinline__ uint32_t f2tf(float f)
{
    uint32_t u;
    asm("cvt.rna.tf32.f32 %0, %1;" : "=r"(u) : "f"(f));
    return u;
}

__device__ __forceinline__ void mma_tf32(float d[4], const uint32_t a[4], const uint32_t b[2])
{
    asm volatile(
        "mma.sync.aligned.m16n8k8.row.col.f32.tf32.tf32.f32 "
        "{%0,%1,%2,%3}, {%4,%5,%6,%7}, {%8,%9}, {%0,%1,%2,%3};"
        : "+f"(d[0]), "+f"(d[1]), "+f"(d[2]), "+f"(d[3])
        : "r"(a[0]), "r"(a[1]), "r"(a[2]), "r"(a[3]), "r"(b[0]), "r"(b[1]));
}

// ---------------------------------------------------------------------------
// FF GEMMs (unchanged from R4 — tf32 tensor cores, validated)
// ---------------------------------------------------------------------------
__global__ __launch_bounds__(256) void gemm1_kernel(
    const int*   __restrict__ x,
    const float* __restrict__ emb,
    const float* __restrict__ W,     // [NS][ND]
    const float* __restrict__ bias)  // [NS]
{
    __shared__ __align__(16) uint32_t As[128][36];
    __shared__ __align__(16) uint32_t Bs[128][36];

    const int tid  = threadIdx.x;
    const int warp = tid >> 5;
    const int lane = tid & 31;
    const int m0c  = blockIdx.y * 128;
    const int n0c  = blockIdx.x * 128;

    const int row = tid >> 1;
    const int kq  = tid & 1;

    const int m   = m0c + row;
    const int bb_ = m & (NB - 1);
    const int tt_ = m >> 8;
    const int tok = x[bb_ * NT + tt_];
    const bool az = (tok == 0);
    const float* arow = emb + (size_t)tok * ND;
    const float* brow = W   + (size_t)(n0c + row) * ND;

    const int wm = (warp & 1) * 64;
    const int wn = (warp >> 1) * 32;
    const int ly = lane >> 2;
    const int lx = lane & 3;

    float acc[4][4][4] = {};

    float4 pa[4], pb[4];
#pragma unroll
    for (int q = 0; q < 4; q++) {
        pa[q] = az ? make_float4(0.f,0.f,0.f,0.f) : *(const float4*)&arow[kq*16 + q*4];
        pb[q] = *(const float4*)&brow[kq*16 + q*4];
    }

    for (int k0 = 0; k0 < ND; k0 += 32) {
#pragma unroll
        for (int q = 0; q < 4; q++) {
            const int c = kq*16 + q*4;
            *(uint4*)&As[row][c] = make_uint4(f2tf(pa[q].x), f2tf(pa[q].y), f2tf(pa[q].z), f2tf(pa[q].w));
            *(uint4*)&Bs[row][c] = make_uint4(f2tf(pb[q].x), f2tf(pb[q].y), f2tf(pb[q].z), f2tf(pb[q].w));
        }
        __syncthreads();
        if (k0 + 32 < ND) {
#pragma unroll
            for (int q = 0; q < 4; q++) {
                pa[q] = az ? make_float4(0.f,0.f,0.f,0.f) : *(const float4*)&arow[k0+32 + kq*16 + q*4];
                pb[q] = *(const float4*)&brow[k0+32 + kq*16 + q*4];
            }
        }
#pragma unroll
        for (int kk = 0; kk < 4; kk++) {
            const int kb = kk * 8;
            uint32_t af[4][4], bf[4][2];
#pragma unroll
            for (int mf = 0; mf < 4; mf++) {
                const int rb = wm + mf*16 + ly;
                af[mf][0] = As[rb    ][kb + lx];
                af[mf][1] = As[rb + 8][kb + lx];
                af[mf][2] = As[rb    ][kb + lx + 4];
                af[mf][3] = As[rb + 8][kb + lx + 4];
            }
#pragma unroll
            for (int nf = 0; nf < 4; nf++) {
                const int nb = wn + nf*8 + ly;
                bf[nf][0] = Bs[nb][kb + lx];
                bf[nf][1] = Bs[nb][kb + lx + 4];
            }
#pragma unroll
            for (int mf = 0; mf < 4; mf++)
#pragma unroll
                for (int nf = 0; nf < 4; nf++)
                    mma_tf32(acc[mf][nf], af[mf], bf[nf]);
        }
        __syncthreads();
    }

#pragma unroll
    for (int nf = 0; nf < 4; nf++) {
        const int gn = n0c + wn + nf*8 + lx*2;
        const float2 bv = *(const float2*)&bias[gn];
#pragma unroll
        for (int mf = 0; mf < 4; mf++) {
            const int gm0 = m0c + wm + mf*16 + ly;
            float2 o0, o1;
            o0.x = fmaxf(acc[mf][nf][0] + bv.x, 0.f);
            o0.y = fmaxf(acc[mf][nf][1] + bv.y, 0.f);
            o1.x = fmaxf(acc[mf][nf][2] + bv.x, 0.f);
            o1.y = fmaxf(acc[mf][nf][3] + bv.y, 0.f);
            *(float2*)&g_C1[(size_t)gm0*NS + gn]       = o0;
            *(float2*)&g_C1[(size_t)(gm0+8)*NS + gn]   = o1;
        }
    }
}

__global__ __launch_bounds__(256) void gemm2_kernel(
    const float* __restrict__ W,     // [ND][NS]
    const float* __restrict__ bias)  // [ND]
{
    __shared__ __align__(16) uint32_t As[128][36];
    __shared__ __align__(16) uint32_t Bs[128][36];

    const int tid  = threadIdx.x;
    const int warp = tid >> 5;
    const int lane = tid & 31;
    const int m0c  = blockIdx.y * 128;
    const int n0c  = blockIdx.x * 128;

    const int row = tid >> 1;
    const int kq  = tid & 1;

    const float* arow = g_C1 + (size_t)(m0c + row) * NS;
    const float* brow = W    + (size_t)(n0c + row) * NS;

    const int wm = (warp & 1) * 64;
    const int wn = (warp >> 1) * 32;
    const int ly = lane >> 2;
    const int lx = lane & 3;

    float acc[4][4][4] = {};

    float4 pa[4], pb[4];
#pragma unroll
    for (int q = 0; q < 4; q++) {
        pa[q] = *(const float4*)&arow[kq*16 + q*4];
        pb[q] = *(const float4*)&brow[kq*16 + q*4];
    }

    for (int k0 = 0; k0 < NS; k0 += 32) {
#pragma unroll
        for (int q = 0; q < 4; q++) {
            const int c = kq*16 + q*4;
            *(uint4*)&As[row][c] = make_uint4(f2tf(pa[q].x), f2tf(pa[q].y), f2tf(pa[q].z), f2tf(pa[q].w));
            *(uint4*)&Bs[row][c] = make_uint4(f2tf(pb[q].x), f2tf(pb[q].y), f2tf(pb[q].z), f2tf(pb[q].w));
        }
        __syncthreads();
        if (k0 + 32 < NS) {
#pragma unroll
            for (int q = 0; q < 4; q++) {
                pa[q] = *(const float4*)&arow[k0+32 + kq*16 + q*4];
                pb[q] = *(const float4*)&brow[k0+32 + kq*16 + q*4];
            }
        }
#pragma unroll
        for (int kk = 0; kk < 4; kk++) {
            const int kb = kk * 8;
            uint32_t af[4][4], bf[4][2];
#pragma unroll
            for (int mf = 0; mf < 4; mf++) {
                const int rb = wm + mf*16 + ly;
                af[mf][0] = As[rb    ][kb + lx];
                af[mf][1] = As[rb + 8][kb + lx];
                af[mf][2] = As[rb    ][kb + lx + 4];
                af[mf][3] = As[rb + 8][kb + lx + 4];
            }
#pragma unroll
            for (int nf = 0; nf < 4; nf++) {
                const int nb = wn + nf*8 + ly;
                bf[nf][0] = Bs[nb][kb + lx];
                bf[nf][1] = Bs[nb][kb + lx + 4];
            }
#pragma unroll
            for (int mf = 0; mf < 4; mf++)
#pragma unroll
                for (int nf = 0; nf < 4; nf++)
                    mma_tf32(acc[mf][nf], af[mf], bf[nf]);
        }
        __syncthreads();
    }

#pragma unroll
    for (int nf = 0; nf < 4; nf++) {
        const int gn = n0c + wn + nf*8 + lx*2;
        const float2 bv = *(const float2*)&bias[gn];
#pragma unroll
        for (int mf = 0; mf < 4; mf++) {
            const int gm0 = m0c + wm + mf*16 + ly;
            float2 o0, o1;
            o0.x = fmaxf(acc[mf][nf][0] + bv.x, 0.f);
            o0.y = fmaxf(acc[mf][nf][1] + bv.y, 0.f);
            o1.x = fmaxf(acc[mf][nf][2] + bv.x, 0.f);
            o1.y = fmaxf(acc[mf][nf][3] + bv.y, 0.f);
            *(float2*)&g_L[(size_t)gm0*ND + gn]       = o0;
            *(float2*)&g_L[(size_t)(gm0+8)*ND + gn]   = o1;
        }
    }
}

// ---------------------------------------------------------------------------
// Barrier flag reset (graph replays reuse state)
// ---------------------------------------------------------------------------
__global__ void init_bar_kernel()
{
    if (threadIdx.x < 8) g_flag[threadIdx.x] = 0u;
}

// ---------------------------------------------------------------------------
// Persistent recurrent kernel with tf32 tensor cores (3xTF32 accuracy).
// 128 CTAs = 8 m-blocks x 16 n-blocks; CTA tile 32(M) x 32(N), K=512.
// 256 threads = 8 warps in 2(M) x 4(N); warp tile 16m x 8n.
// W_hid slice split hi/lo into smem once. h tile staged fp32, split on the fly.
// m-blocks are independent chains -> per-m-block flag barrier (16 arrivals).
// ---------------------------------------------------------------------------
__global__ __launch_bounds__(256, 1) void step_persist(
    const float* __restrict__ Wh,     // [ND][ND]
    const float* __restrict__ bhid)   // [ND]
{
    extern __shared__ float sm[];
    float* Whi = sm;                  // [32][SROW]
    float* Wlo = sm + 32*SROW;        // [32][SROW]
    float* hs  = sm + 64*SROW;        // [32][SROW]

    const int tid  = threadIdx.x;
    const int bx   = blockIdx.x;
    const int mb   = bx >> 4;          // 0..7
    const int nb   = bx & 15;          // 0..15
    const int m0   = mb * 32;
    const int n0   = nb * 32;
    const int warp = tid >> 5;
    const int lane = tid & 31;
    const int wm   = (warp & 1) * 16;
    const int wn   = (warp >> 1) * 8;
    const int ly   = lane >> 2;
    const int lx   = lane & 3;

    // --- split W slice hi/lo into smem once ---
#pragma unroll
    for (int i = 0; i < 16; i++) {
        const int idx = tid + i*256;       // 0..4095 float4 slots
        const int r   = idx >> 7;          // 0..31
        const int c4  = idx & 127;
        float4 w = *(const float4*)&Wh[(size_t)(n0+r)*ND + c4*4];
        float hx = __uint_as_float(f2tf(w.x));
        float hy = __uint_as_float(f2tf(w.y));
        float hz = __uint_as_float(f2tf(w.z));
        float hw = __uint_as_float(f2tf(w.w));
        float* ph = &Whi[r*SROW + c4*4];
        float* pl = &Wlo[r*SROW + c4*4];
        ph[0]=hx; ph[1]=hy; ph[2]=hz; ph[3]=hw;
        pl[0]=w.x-hx; pl[1]=w.y-hy; pl[2]=w.z-hz; pl[3]=w.w-hw;
    }
    const int gnc = n0 + wn + lx*2;
    const float bb0 = bhid[gnc];
    const float bb1 = bhid[gnc + 1];
    const int gm0 = m0 + wm + ly;          // epilogue rows gm0, gm0+8
    __syncthreads();

    for (int t = 0; t < NT; t++) {
        const float* __restrict__ Lt   = g_L + (size_t)t * NB * ND;
        float*       __restrict__ hout = g_h[(t+1) & 1];

        // prefetch L microtile
        const float2 l0 = __ldg((const float2*)&Lt[(size_t)gm0*ND + gnc]);
        const float2 l1 = __ldg((const float2*)&Lt[(size_t)(gm0+8)*ND + gnc]);

        float acc[4] = {0.f, 0.f, 0.f, 0.f};
        float cor[4] = {0.f, 0.f, 0.f, 0.f};
        if (t > 0) {
            const float* __restrict__ hin = g_h[t & 1];
            // stage h tile (bypass L1: written by peer SMs last step)
#pragma unroll
            for (int i = 0; i < 16; i++) {
                const int idx = tid + i*256;
                const int r   = idx >> 7;
                const int c4  = idx & 127;
                float4 v = __ldcg((const float4*)&hin[(size_t)(m0+r)*ND + c4*4]);
                *(float4*)&hs[r*SROW + c4*4] = v;
            }
            __syncthreads();

            const float* ar0 = &hs[(wm+ly)*SROW];
            const float* ar1 = &hs[(wm+ly+8)*SROW];
            const float* bh0 = &Whi[(wn+ly)*SROW];
            const float* bl0 = &Wlo[(wn+ly)*SROW];

#pragma unroll 4
            for (int kc = 0; kc < 64; kc++) {
                const int kb = kc*8;
                float a0 = ar0[kb+lx], a1 = ar1[kb+lx];
                float a2 = ar0[kb+lx+4], a3 = ar1[kb+lx+4];
                uint32_t ah[4], al[4], bhf[2], blf[2];
                ah[0] = f2tf(a0); al[0] = __float_as_uint(a0 - __uint_as_float(ah[0]));
                ah[1] = f2tf(a1); al[1] = __float_as_uint(a1 - __uint_as_float(ah[1]));
                ah[2] = f2tf(a2); al[2] = __float_as_uint(a2 - __uint_as_float(ah[2]));
                ah[3] = f2tf(a3); al[3] = __float_as_uint(a3 - __uint_as_float(ah[3]));
                bhf[0] = __float_as_uint(bh0[kb+lx]);
                bhf[1] = __float_as_uint(bh0[kb+lx+4]);
                blf[0] = __float_as_uint(bl0[kb+lx]);
                blf[1] = __float_as_uint(bl0[kb+lx+4]);
                mma_tf32(acc, ah, bhf);     // main term
                mma_tf32(cor, al, bhf);     // h residual
                mma_tf32(cor, ah, blf);     // W residual
            }
        }

        // epilogue: +corr +L +bias, tanh, store
        {
            float2 o0, o1;
            o0.x = tanhf(acc[0] + cor[0] + l0.x + bb0);
            o0.y = tanhf(acc[1] + cor[1] + l0.y + bb1);
            o1.x = tanhf(acc[2] + cor[2] + l1.x + bb0);
            o1.y = tanhf(acc[3] + cor[3] + l1.y + bb1);
            *(float2*)&hout[(size_t)gm0*ND + gnc]     = o0;
            *(float2*)&hout[(size_t)(gm0+8)*ND + gnc] = o1;
        }

        // per-m-block barrier (16 CTAs); also guards hs WAR for next step
        __threadfence();
        __syncthreads();
        if (tid == 0) {
            const unsigned target = (unsigned)(t + 1) * 16u;
            atomicAdd(&g_flag[mb], 1u);
            while (*((volatile unsigned*)&g_flag[mb]) < target) { }
        }
        __syncthreads();
    }
}

// ---------------------------------------------------------------------------
// Row L2-normalize final h (g_h[0] after 128 steps)
// ---------------------------------------------------------------------------
__global__ __launch_bounds__(128) void norm_kernel(float* __restrict__ out)
{
    __shared__ float red[4];
    const int row = blockIdx.x;
    const int tid = threadIdx.x;

    const float* h = g_h[0] + (size_t)row * ND;
    float4 v = *(const float4*)&h[tid * 4];
    float s = v.x*v.x + v.y*v.y + v.z*v.z + v.w*v.w;
#pragma unroll
    for (int o = 16; o; o >>= 1) s += __shfl_xor_sync(0xFFFFFFFFu, s, o);
    if ((tid & 31) == 0) red[tid >> 5] = s;
    __syncthreads();
    const float tot = red[0] + red[1] + red[2] + red[3];
    const float inv = 1.f / fmaxf(sqrtf(tot), 1e-12f);
    float4 o4 = make_float4(v.x*inv, v.y*inv, v.z*inv, v.w*inv);
    *(float4*)&out[(size_t)row * ND + tid * 4] = o4;
}

// ---------------------------------------------------------------------------
// Launch
// ---------------------------------------------------------------------------
extern "C" void kernel_launch(void* const* d_in, const int* in_sizes, int n_in,
                              void* d_out, int out_size)
{
    const int*   x     = (const int*)  d_in[0];
    const float* emb   = (const float*)d_in[1];
    const float* W_inp = (const float*)d_in[2];
    const float* b_inp = (const float*)d_in[3];
    const float* W_mid = (const float*)d_in[4];
    const float* b_mid = (const float*)d_in[5];
    const float* W_hid = (const float*)d_in[6];
    const float* b_hid = (const float*)d_in[7];
    float* out = (float*)d_out;

    cudaFuncSetAttribute(step_persist, cudaFuncAttributeMaxDynamicSharedMemorySize, STEP_SMEM);

    // Feed-forward part for ALL timesteps (tensor cores, tf32)
    gemm1_kernel<<<dim3(NS/128, NM/128), 256>>>(x, emb, W_inp, b_inp);
    gemm2_kernel<<<dim3(ND/128, NM/128), 256>>>(W_mid, b_mid);

    // Recurrence: persistent kernel, per-m-block barriers, 3xTF32 mma
    init_bar_kernel<<<1, 32>>>();
    step_persist<<<SGRID, 256, STEP_SMEM>>>(W_hid, b_hid);

    norm_kernel<<<NB, 128>>>(out);
}

// round 6
// speedup vs baseline: 2.6797x; 1.2955x over previous
#include <cuda_runtime.h>
#include <cuda_bf16.h>
#include <math.h>
#include <stdint.h>

// Problem dims (fixed by the reference)
#define NB 256            // batch
#define NT 128            // seq len
#define ND 512            // embed dim
#define NS 256            // shrink dim
#define NM (NB*NT)        // 32768 flattened (t,b) rows

#define SGRID 128         // step kernel CTAs: 8 m-blocks x 16 n-blocks
#define PROW 260          // padded smem row in bf16-PAIRS (256 + 4)
// 4 arrays of [32][PROW] uint32 (bf16 pairs): Ws0, Ws1, hs0, hs1
#define STEP_SMEM (4 * 32 * PROW * 4)

// ---------------------------------------------------------------------------
// Scratch (device globals; no runtime allocation allowed)
// ---------------------------------------------------------------------------
__device__ float g_C1[(size_t)NM * NS];     // relu(E @ W_inp^T + b_inp)
__device__ float g_L [(size_t)NM * ND];     // relu(C1 @ W_mid^T + b_mid)  [t][b][512]
__device__ __nv_bfloat16 g_h0[2][(size_t)NB * ND];  // h main part (bf16), ping-pong
__device__ __nv_bfloat16 g_h1[2][(size_t)NB * ND];  // h residual part (bf16)
__device__ unsigned g_flag[8];              // per-m-block step counters

// ---------------------------------------------------------------------------
// mma helpers
// ---------------------------------------------------------------------------
__device__ __forceinline__ uint32_t f2tf(float f)
{
    uint32_t u;
    asm("cvt.rna.tf32.f32 %0, %1;" : "=r"(u) : "f"(f));
    return u;
}

__device__ __forceinline__ void mma_tf32(float d[4], const uint32_t a[4], const uint32_t b[2])
{
    asm volatile(
        "mma.sync.aligned.m16n8k8.row.col.f32.tf32.tf32.f32 "
        "{%0,%1,%2,%3}, {%4,%5,%6,%7}, {%8,%9}, {%0,%1,%2,%3};"
        : "+f"(d[0]), "+f"(d[1]), "+f"(d[2]), "+f"(d[3])
        : "r"(a[0]), "r"(a[1]), "r"(a[2]), "r"(a[3]), "r"(b[0]), "r"(b[1]));
}

__device__ __forceinline__ void mma_bf16(float d[4], const uint32_t a[4], const uint32_t b[2])
{
    asm volatile(
        "mma.sync.aligned.m16n8k16.row.col.f32.bf16.bf16.f32 "
        "{%0,%1,%2,%3}, {%4,%5,%6,%7}, {%8,%9}, {%0,%1,%2,%3};"
        : "+f"(d[0]), "+f"(d[1]), "+f"(d[2]), "+f"(d[3])
        : "r"(a[0]), "r"(a[1]), "r"(a[2]), "r"(a[3]), "r"(b[0]), "r"(b[1]));
}

// ---------------------------------------------------------------------------
// FF GEMMs (unchanged from R4/R5 — tf32 tensor cores, validated)
// ---------------------------------------------------------------------------
__global__ __launch_bounds__(256) void gemm1_kernel(
    const int*   __restrict__ x,
    const float* __restrict__ emb,
    const float* __restrict__ W,     // [NS][ND]
    const float* __restrict__ bias)  // [NS]
{
    __shared__ __align__(16) uint32_t As[128][36];
    __shared__ __align__(16) uint32_t Bs[128][36];

    const int tid  = threadIdx.x;
    const int warp = tid >> 5;
    const int lane = tid & 31;
    const int m0c  = blockIdx.y * 128;
    const int n0c  = blockIdx.x * 128;

    const int row = tid >> 1;
    const int kq  = tid & 1;

    const int m   = m0c + row;
    const int bb_ = m & (NB - 1);
    const int tt_ = m >> 8;
    const int tok = x[bb_ * NT + tt_];
    const bool az = (tok == 0);
    const float* arow = emb + (size_t)tok * ND;
    const float* brow = W   + (size_t)(n0c + row) * ND;

    const int wm = (warp & 1) * 64;
    const int wn = (warp >> 1) * 32;
    const int ly = lane >> 2;
    const int lx = lane & 3;

    float acc[4][4][4] = {};

    float4 pa[4], pb[4];
#pragma unroll
    for (int q = 0; q < 4; q++) {
        pa[q] = az ? make_float4(0.f,0.f,0.f,0.f) : *(const float4*)&arow[kq*16 + q*4];
        pb[q] = *(const float4*)&brow[kq*16 + q*4];
    }

    for (int k0 = 0; k0 < ND; k0 += 32) {
#pragma unroll
        for (int q = 0; q < 4; q++) {
            const int c = kq*16 + q*4;
            *(uint4*)&As[row][c] = make_uint4(f2tf(pa[q].x), f2tf(pa[q].y), f2tf(pa[q].z), f2tf(pa[q].w));
            *(uint4*)&Bs[row][c] = make_uint4(f2tf(pb[q].x), f2tf(pb[q].y), f2tf(pb[q].z), f2tf(pb[q].w));
        }
        __syncthreads();
        if (k0 + 32 < ND) {
#pragma unroll
            for (int q = 0; q < 4; q++) {
                pa[q] = az ? make_float4(0.f,0.f,0.f,0.f) : *(const float4*)&arow[k0+32 + kq*16 + q*4];
                pb[q] = *(const float4*)&brow[k0+32 + kq*16 + q*4];
            }
        }
#pragma unroll
        for (int kk = 0; kk < 4; kk++) {
            const int kb = kk * 8;
            uint32_t af[4][4], bf[4][2];
#pragma unroll
            for (int mf = 0; mf < 4; mf++) {
                const int rb = wm + mf*16 + ly;
                af[mf][0] = As[rb    ][kb + lx];
                af[mf][1] = As[rb + 8][kb + lx];
                af[mf][2] = As[rb    ][kb + lx + 4];
                af[mf][3] = As[rb + 8][kb + lx + 4];
            }
#pragma unroll
            for (int nf = 0; nf < 4; nf++) {
                const int nb = wn + nf*8 + ly;
                bf[nf][0] = Bs[nb][kb + lx];
                bf[nf][1] = Bs[nb][kb + lx + 4];
            }
#pragma unroll
            for (int mf = 0; mf < 4; mf++)
#pragma unroll
                for (int nf = 0; nf < 4; nf++)
                    mma_tf32(acc[mf][nf], af[mf], bf[nf]);
        }
        __syncthreads();
    }

#pragma unroll
    for (int nf = 0; nf < 4; nf++) {
        const int gn = n0c + wn + nf*8 + lx*2;
        const float2 bv = *(const float2*)&bias[gn];
#pragma unroll
        for (int mf = 0; mf < 4; mf++) {
            const int gm0 = m0c + wm + mf*16 + ly;
            float2 o0, o1;
            o0.x = fmaxf(acc[mf][nf][0] + bv.x, 0.f);
            o0.y = fmaxf(acc[mf][nf][1] + bv.y, 0.f);
            o1.x = fmaxf(acc[mf][nf][2] + bv.x, 0.f);
            o1.y = fmaxf(acc[mf][nf][3] + bv.y, 0.f);
            *(float2*)&g_C1[(size_t)gm0*NS + gn]       = o0;
            *(float2*)&g_C1[(size_t)(gm0+8)*NS + gn]   = o1;
        }
    }
}

__global__ __launch_bounds__(256) void gemm2_kernel(
    const float* __restrict__ W,     // [ND][NS]
    const float* __restrict__ bias)  // [ND]
{
    __shared__ __align__(16) uint32_t As[128][36];
    __shared__ __align__(16) uint32_t Bs[128][36];

    const int tid  = threadIdx.x;
    const int warp = tid >> 5;
    const int lane = tid & 31;
    const int m0c  = blockIdx.y * 128;
    const int n0c  = blockIdx.x * 128;

    const int row = tid >> 1;
    const int kq  = tid & 1;

    const float* arow = g_C1 + (size_t)(m0c + row) * NS;
    const float* brow = W    + (size_t)(n0c + row) * NS;

    const int wm = (warp & 1) * 64;
    const int wn = (warp >> 1) * 32;
    const int ly = lane >> 2;
    const int lx = lane & 3;

    float acc[4][4][4] = {};

    float4 pa[4], pb[4];
#pragma unroll
    for (int q = 0; q < 4; q++) {
        pa[q] = *(const float4*)&arow[kq*16 + q*4];
        pb[q] = *(const float4*)&brow[kq*16 + q*4];
    }

    for (int k0 = 0; k0 < NS; k0 += 32) {
#pragma unroll
        for (int q = 0; q < 4; q++) {
            const int c = kq*16 + q*4;
            *(uint4*)&As[row][c] = make_uint4(f2tf(pa[q].x), f2tf(pa[q].y), f2tf(pa[q].z), f2tf(pa[q].w));
            *(uint4*)&Bs[row][c] = make_uint4(f2tf(pb[q].x), f2tf(pb[q].y), f2tf(pb[q].z), f2tf(pb[q].w));
        }
        __syncthreads();
        if (k0 + 32 < NS) {
#pragma unroll
            for (int q = 0; q < 4; q++) {
                pa[q] = *(const float4*)&arow[k0+32 + kq*16 + q*4];
                pb[q] = *(const float4*)&brow[k0+32 + kq*16 + q*4];
            }
        }
#pragma unroll
        for (int kk = 0; kk < 4; kk++) {
            const int kb = kk * 8;
            uint32_t af[4][4], bf[4][2];
#pragma unroll
            for (int mf = 0; mf < 4; mf++) {
                const int rb = wm + mf*16 + ly;
                af[mf][0] = As[rb    ][kb + lx];
                af[mf][1] = As[rb + 8][kb + lx];
                af[mf][2] = As[rb    ][kb + lx + 4];
                af[mf][3] = As[rb + 8][kb + lx + 4];
            }
#pragma unroll
            for (int nf = 0; nf < 4; nf++) {
                const int nb = wn + nf*8 + ly;
                bf[nf][0] = Bs[nb][kb + lx];
                bf[nf][1] = Bs[nb][kb + lx + 4];
            }
#pragma unroll
            for (int mf = 0; mf < 4; mf++)
#pragma unroll
                for (int nf = 0; nf < 4; nf++)
                    mma_tf32(acc[mf][nf], af[mf], bf[nf]);
        }
        __syncthreads();
    }

#pragma unroll
    for (int nf = 0; nf < 4; nf++) {
        const int gn = n0c + wn + nf*8 + lx*2;
        const float2 bv = *(const float2*)&bias[gn];
#pragma unroll
        for (int mf = 0; mf < 4; mf++) {
            const int gm0 = m0c + wm + mf*16 + ly;
            float2 o0, o1;
            o0.x = fmaxf(acc[mf][nf][0] + bv.x, 0.f);
            o0.y = fmaxf(acc[mf][nf][1] + bv.y, 0.f);
            o1.x = fmaxf(acc[mf][nf][2] + bv.x, 0.f);
            o1.y = fmaxf(acc[mf][nf][3] + bv.y, 0.f);
            *(float2*)&g_L[(size_t)gm0*ND + gn]       = o0;
            *(float2*)&g_L[(size_t)(gm0+8)*ND + gn]   = o1;
        }
    }
}

// ---------------------------------------------------------------------------
// Barrier flag reset (graph replays reuse state)
// ---------------------------------------------------------------------------
__global__ void init_bar_kernel()
{
    if (threadIdx.x < 8) g_flag[threadIdx.x] = 0u;
}

// ---------------------------------------------------------------------------
// Persistent recurrent kernel, bf16x2 split-precision mma (m16n8k16).
// 128 CTAs = 8 m-blocks x 16 n-blocks; CTA tile 32(M) x 32(N), K=512.
// 256 threads = 8 warps in 2(M) x 4(N); warp tile 16m x 8n.
// W_hid split (bf16 hi/lo) into smem once; h stored split in global by the
// epilogue, staged into smem per step. Inner loop: pure LDS + 3 mma per k16.
// acc = a0*b0 (main), cor = a1*b0 + a0*b1 (residuals); error ~2^-16.
// ---------------------------------------------------------------------------
__global__ __launch_bounds__(256, 1) void step_persist(
    const float* __restrict__ Wh,     // [ND][ND]
    const float* __restrict__ bhid)   // [ND]
{
    extern __shared__ uint32_t smu[]; // bf16 PAIRS, row stride PROW
    uint32_t* Ws0 = smu;              // [32][PROW] W main
    uint32_t* Ws1 = smu + 32*PROW;    // [32][PROW] W residual
    uint32_t* hs0 = smu + 64*PROW;    // [32][PROW] h main
    uint32_t* hs1 = smu + 96*PROW;    // [32][PROW] h residual

    const int tid  = threadIdx.x;
    const int bx   = blockIdx.x;
    const int mb   = bx >> 4;          // 0..7
    const int m0   = mb * 32;
    const int n0   = (bx & 15) * 32;
    const int warp = tid >> 5;
    const int lane = tid & 31;
    const int wm   = (warp & 1) * 16;
    const int wn   = (warp >> 1) * 8;
    const int ly   = lane >> 2;
    const int lx   = lane & 3;

    // --- split W slice into bf16 hi/lo pairs in smem (once) ---
#pragma unroll
    for (int i = 0; i < 32; i++) {
        const int idx = tid + i*256;        // 0..8191 pair slots (32 rows x 256)
        const int r   = idx >> 8;
        const int p   = idx & 255;          // pair col (2 k values)
        float2 w = *(const float2*)&Wh[(size_t)(n0+r)*ND + p*2];
        __nv_bfloat16 h0x = __float2bfloat16_rn(w.x);
        __nv_bfloat16 h0y = __float2bfloat16_rn(w.y);
        float rx = w.x - __bfloat162float(h0x);
        float ry = w.y - __bfloat162float(h0y);
        __nv_bfloat162 p0; p0.x = h0x; p0.y = h0y;
        __nv_bfloat162 p1; p1.x = __float2bfloat16_rn(rx); p1.y = __float2bfloat16_rn(ry);
        Ws0[r*PROW + p] = *(uint32_t*)&p0;
        Ws1[r*PROW + p] = *(uint32_t*)&p1;
    }
    const int gnc = n0 + wn + lx*2;
    const float bb0 = bhid[gnc];
    const float bb1 = bhid[gnc + 1];
    const int gm0 = m0 + wm + ly;          // epilogue rows gm0, gm0+8
    __syncthreads();

    for (int t = 0; t < NT; t++) {
        const float* __restrict__ Lt = g_L + (size_t)t * NB * ND;
        __nv_bfloat16* __restrict__ ho0 = g_h0[(t+1) & 1];
        __nv_bfloat16* __restrict__ ho1 = g_h1[(t+1) & 1];

        // prefetch L microtile
        const float2 l0 = __ldg((const float2*)&Lt[(size_t)gm0*ND + gnc]);
        const float2 l1 = __ldg((const float2*)&Lt[(size_t)(gm0+8)*ND + gnc]);

        float acc[4] = {0.f, 0.f, 0.f, 0.f};
        float cor[4] = {0.f, 0.f, 0.f, 0.f};
        if (t > 0) {
            const __nv_bfloat16* __restrict__ hi0 = g_h0[t & 1];
            const __nv_bfloat16* __restrict__ hi1 = g_h1[t & 1];
            // stage h tiles (bypass L1: written by peer SMs last step)
            // each array: 32 rows x 64 uint4 (512 bf16/row) = 2048 uint4
#pragma unroll
            for (int i = 0; i < 8; i++) {
                const int idx = tid + i*256;
                const int r   = idx >> 6;
                const int c4  = idx & 63;
                uint4 v = __ldcg((const uint4*)(hi0 + (size_t)(m0+r)*ND) + c4);
                *(uint4*)&hs0[r*PROW + c4*4] = v;
            }
#pragma unroll
            for (int i = 0; i < 8; i++) {
                const int idx = tid + i*256;
                const int r   = idx >> 6;
                const int c4  = idx & 63;
                uint4 v = __ldcg((const uint4*)(hi1 + (size_t)(m0+r)*ND) + c4);
                *(uint4*)&hs1[r*PROW + c4*4] = v;
            }
            __syncthreads();

            const uint32_t* a0r = &hs0[(wm+ly)*PROW + lx];
            const uint32_t* a1r = &hs0[(wm+ly+8)*PROW + lx];
            const uint32_t* c0r = &hs1[(wm+ly)*PROW + lx];
            const uint32_t* c1r = &hs1[(wm+ly+8)*PROW + lx];
            const uint32_t* b0r = &Ws0[(wn+ly)*PROW + lx];
            const uint32_t* b1r = &Ws1[(wn+ly)*PROW + lx];

#pragma unroll 8
            for (int kc = 0; kc < 32; kc++) {     // k16 chunks (8 pairs each)
                const int pp = kc*8;
                uint32_t a[4], al[4], bh[2], bl[2];
                a[0]  = a0r[pp];     a[1]  = a1r[pp];
                a[2]  = a0r[pp + 4]; a[3]  = a1r[pp + 4];
                al[0] = c0r[pp];     al[1] = c1r[pp];
                al[2] = c0r[pp + 4]; al[3] = c1r[pp + 4];
                bh[0] = b0r[pp];     bh[1] = b0r[pp + 4];
                bl[0] = b1r[pp];     bl[1] = b1r[pp + 4];
                mma_bf16(acc, a,  bh);   // main
                mma_bf16(cor, al, bh);   // h residual
                mma_bf16(cor, a,  bl);   // W residual
            }
        }

        // epilogue: +corr +L +bias, tanh, split to bf16 pair, store
        {
            float o00 = tanhf(acc[0] + cor[0] + l0.x + bb0);
            float o01 = tanhf(acc[1] + cor[1] + l0.y + bb1);
            float o10 = tanhf(acc[2] + cor[2] + l1.x + bb0);
            float o11 = tanhf(acc[3] + cor[3] + l1.y + bb1);

            __nv_bfloat162 h00, h01, r00, r01;
            h00.x = __float2bfloat16_rn(o00);
            h00.y = __float2bfloat16_rn(o01);
            r00.x = __float2bfloat16_rn(o00 - __bfloat162float(h00.x));
            r00.y = __float2bfloat16_rn(o01 - __bfloat162float(h00.y));
            h01.x = __float2bfloat16_rn(o10);
            h01.y = __float2bfloat16_rn(o11);
            r01.x = __float2bfloat16_rn(o10 - __bfloat162float(h01.x));
            r01.y = __float2bfloat16_rn(o11 - __bfloat162float(h01.y));

            *(uint32_t*)&ho0[(size_t)gm0*ND + gnc]     = *(uint32_t*)&h00;
            *(uint32_t*)&ho1[(size_t)gm0*ND + gnc]     = *(uint32_t*)&r00;
            *(uint32_t*)&ho0[(size_t)(gm0+8)*ND + gnc] = *(uint32_t*)&h01;
            *(uint32_t*)&ho1[(size_t)(gm0+8)*ND + gnc] = *(uint32_t*)&r01;
        }

        // per-m-block barrier (16 CTAs); also guards hs WAR for next step
        __threadfence();
        __syncthreads();
        if (tid == 0) {
            const unsigned target = (unsigned)(t + 1) * 16u;
            atomicAdd(&g_flag[mb], 1u);
            while (*((volatile unsigned*)&g_flag[mb]) < target) { }
        }
        __syncthreads();
    }
}

// ---------------------------------------------------------------------------
// Row L2-normalize final h (split arrays, index 0 after even NT)
// ---------------------------------------------------------------------------
__global__ __launch_bounds__(128) void norm_kernel(float* __restrict__ out)
{
    __shared__ float red[4];
    const int row = blockIdx.x;
    const int tid = threadIdx.x;   // each covers 4 cols

    const __nv_bfloat162* h0 = (const __nv_bfloat162*)(g_h0[0] + (size_t)row * ND);
    const __nv_bfloat162* h1 = (const __nv_bfloat162*)(g_h1[0] + (size_t)row * ND);
    __nv_bfloat162 a0 = h0[tid*2], a1 = h0[tid*2+1];
    __nv_bfloat162 b0 = h1[tid*2], b1 = h1[tid*2+1];
    float4 v;
    v.x = __bfloat162float(a0.x) + __bfloat162float(b0.x);
    v.y = __bfloat162float(a0.y) + __bfloat162float(b0.y);
    v.z = __bfloat162float(a1.x) + __bfloat162float(b1.x);
    v.w = __bfloat162float(a1.y) + __bfloat162float(b1.y);

    float s = v.x*v.x + v.y*v.y + v.z*v.z + v.w*v.w;
#pragma unroll
    for (int o = 16; o; o >>= 1) s += __shfl_xor_sync(0xFFFFFFFFu, s, o);
    if ((tid & 31) == 0) red[tid >> 5] = s;
    __syncthreads();
    const float tot = red[0] + red[1] + red[2] + red[3];
    const float inv = 1.f / fmaxf(sqrtf(tot), 1e-12f);
    float4 o4 = make_float4(v.x*inv, v.y*inv, v.z*inv, v.w*inv);
    *(float4*)&out[(size_t)row * ND + tid * 4] = o4;
}

// ---------------------------------------------------------------------------
// Launch
// ---------------------------------------------------------------------------
extern "C" void kernel_launch(void* const* d_in, const int* in_sizes, int n_in,
                              void* d_out, int out_size)
{
    const int*   x     = (const int*)  d_in[0];
    const float* emb   = (const float*)d_in[1];
    const float* W_inp = (const float*)d_in[2];
    const float* b_inp = (const float*)d_in[3];
    const float* W_mid = (const float*)d_in[4];
    const float* b_mid = (const float*)d_in[5];
    const float* W_hid = (const float*)d_in[6];
    const float* b_hid = (const float*)d_in[7];
    float* out = (float*)d_out;

    cudaFuncSetAttribute(step_persist, cudaFuncAttributeMaxDynamicSharedMemorySize, STEP_SMEM);

    // Feed-forward part for ALL timesteps (tensor cores, tf32)
    gemm1_kernel<<<dim3(NS/128, NM/128), 256>>>(x, emb, W_inp, b_inp);
    gemm2_kernel<<<dim3(ND/128, NM/128), 256>>>(W_mid, b_mid);

    // Recurrence: persistent kernel, per-m-block barriers, bf16x2 mma
    init_bar_kernel<<<1, 32>>>();
    step_persist<<<SGRID, 256, STEP_SMEM>>>(W_hid, b_hid);

    norm_kernel<<<NB, 128>>>(out);
}

// round 7
// speedup vs baseline: 2.8116x; 1.0492x over previous
#include <cuda_runtime.h>
#include <cuda_bf16.h>
#include <math.h>
#include <stdint.h>

// Problem dims (fixed by the reference)
#define NB 256            // batch
#define NT 128            // seq len
#define ND 512            // embed dim
#define NS 256            // shrink dim
#define NM (NB*NT)        // 32768 flattened (t,b) rows

#define SGRID 128         // step kernel CTAs: 8 m-blocks x 16 n-blocks
#define PROW 260          // padded smem row in bf16-PAIRS (256 + 4)
// 4 arrays of [32][PROW] uint32 (bf16 pairs): Ws0, Ws1, hs0, hs1
#define STEP_SMEM (4 * 32 * PROW * 4)

// ---------------------------------------------------------------------------
// Scratch (device globals; no runtime allocation allowed)
// ---------------------------------------------------------------------------
__device__ float g_C1[(size_t)NM * NS];     // relu(E @ W_inp^T + b_inp)
__device__ float g_L [(size_t)NM * ND];     // relu(C1 @ W_mid^T + b_mid)  [t][b][512]
__device__ __nv_bfloat16 g_h0[2][(size_t)NB * ND];  // h main part (bf16), ping-pong
__device__ __nv_bfloat16 g_h1[2][(size_t)NB * ND];  // h residual part (bf16)
__device__ unsigned g_flag[8];              // per-m-block step counters

// ---------------------------------------------------------------------------
// mma / ldmatrix helpers
// ---------------------------------------------------------------------------
__device__ __forceinline__ uint32_t f2tf(float f)
{
    uint32_t u;
    asm("cvt.rna.tf32.f32 %0, %1;" : "=r"(u) : "f"(f));
    return u;
}

__device__ __forceinline__ void mma_tf32(float d[4], const uint32_t a[4], const uint32_t b[2])
{
    asm volatile(
        "mma.sync.aligned.m16n8k8.row.col.f32.tf32.tf32.f32 "
        "{%0,%1,%2,%3}, {%4,%5,%6,%7}, {%8,%9}, {%0,%1,%2,%3};"
        : "+f"(d[0]), "+f"(d[1]), "+f"(d[2]), "+f"(d[3])
        : "r"(a[0]), "r"(a[1]), "r"(a[2]), "r"(a[3]), "r"(b[0]), "r"(b[1]));
}

__device__ __forceinline__ void mma_bf16(float d[4], const uint32_t a[4], const uint32_t b[2])
{
    asm volatile(
        "mma.sync.aligned.m16n8k16.row.col.f32.bf16.bf16.f32 "
        "{%0,%1,%2,%3}, {%4,%5,%6,%7}, {%8,%9}, {%0,%1,%2,%3};"
        : "+f"(d[0]), "+f"(d[1]), "+f"(d[2]), "+f"(d[3])
        : "r"(a[0]), "r"(a[1]), "r"(a[2]), "r"(a[3]), "r"(b[0]), "r"(b[1]));
}

__device__ __forceinline__ void ldsm_x4(uint32_t r[4], uint32_t addr)
{
    asm volatile("ldmatrix.sync.aligned.m8n8.x4.shared.b16 {%0,%1,%2,%3}, [%4];"
        : "=r"(r[0]), "=r"(r[1]), "=r"(r[2]), "=r"(r[3]) : "r"(addr));
}

__device__ __forceinline__ uint32_t smem_u32(const void* p)
{
    return (uint32_t)__cvta_generic_to_shared(p);
}

// ---------------------------------------------------------------------------
// FF GEMMs (unchanged from R4-R6 — tf32 tensor cores, validated)
// ---------------------------------------------------------------------------
__global__ __launch_bounds__(256) void gemm1_kernel(
    const int*   __restrict__ x,
    const float* __restrict__ emb,
    const float* __restrict__ W,     // [NS][ND]
    const float* __restrict__ bias)  // [NS]
{
    __shared__ __align__(16) uint32_t As[128][36];
    __shared__ __align__(16) uint32_t Bs[128][36];

    const int tid  = threadIdx.x;
    const int warp = tid >> 5;
    const int lane = tid & 31;
    const int m0c  = blockIdx.y * 128;
    const int n0c  = blockIdx.x * 128;

    const int row = tid >> 1;
    const int kq  = tid & 1;

    const int m   = m0c + row;
    const int bb_ = m & (NB - 1);
    const int tt_ = m >> 8;
    const int tok = x[bb_ * NT + tt_];
    const bool az = (tok == 0);
    const float* arow = emb + (size_t)tok * ND;
    const float* brow = W   + (size_t)(n0c + row) * ND;

    const int wm = (warp & 1) * 64;
    const int wn = (warp >> 1) * 32;
    const int ly = lane >> 2;
    const int lx = lane & 3;

    float acc[4][4][4] = {};

    float4 pa[4], pb[4];
#pragma unroll
    for (int q = 0; q < 4; q++) {
        pa[q] = az ? make_float4(0.f,0.f,0.f,0.f) : *(const float4*)&arow[kq*16 + q*4];
        pb[q] = *(const float4*)&brow[kq*16 + q*4];
    }

    for (int k0 = 0; k0 < ND; k0 += 32) {
#pragma unroll
        for (int q = 0; q < 4; q++) {
            const int c = kq*16 + q*4;
            *(uint4*)&As[row][c] = make_uint4(f2tf(pa[q].x), f2tf(pa[q].y), f2tf(pa[q].z), f2tf(pa[q].w));
            *(uint4*)&Bs[row][c] = make_uint4(f2tf(pb[q].x), f2tf(pb[q].y), f2tf(pb[q].z), f2tf(pb[q].w));
        }
        __syncthreads();
        if (k0 + 32 < ND) {
#pragma unroll
            for (int q = 0; q < 4; q++) {
                pa[q] = az ? make_float4(0.f,0.f,0.f,0.f) : *(const float4*)&arow[k0+32 + kq*16 + q*4];
                pb[q] = *(const float4*)&brow[k0+32 + kq*16 + q*4];
            }
        }
#pragma unroll
        for (int kk = 0; kk < 4; kk++) {
            const int kb = kk * 8;
            uint32_t af[4][4], bf[4][2];
#pragma unroll
            for (int mf = 0; mf < 4; mf++) {
                const int rb = wm + mf*16 + ly;
                af[mf][0] = As[rb    ][kb + lx];
                af[mf][1] = As[rb + 8][kb + lx];
                af[mf][2] = As[rb    ][kb + lx + 4];
                af[mf][3] = As[rb + 8][kb + lx + 4];
            }
#pragma unroll
            for (int nf = 0; nf < 4; nf++) {
                const int nb = wn + nf*8 + ly;
                bf[nf][0] = Bs[nb][kb + lx];
                bf[nf][1] = Bs[nb][kb + lx + 4];
            }
#pragma unroll
            for (int mf = 0; mf < 4; mf++)
#pragma unroll
                for (int nf = 0; nf < 4; nf++)
                    mma_tf32(acc[mf][nf], af[mf], bf[nf]);
        }
        __syncthreads();
    }

#pragma unroll
    for (int nf = 0; nf < 4; nf++) {
        const int gn = n0c + wn + nf*8 + lx*2;
        const float2 bv = *(const float2*)&bias[gn];
#pragma unroll
        for (int mf = 0; mf < 4; mf++) {
            const int gm0 = m0c + wm + mf*16 + ly;
            float2 o0, o1;
            o0.x = fmaxf(acc[mf][nf][0] + bv.x, 0.f);
            o0.y = fmaxf(acc[mf][nf][1] + bv.y, 0.f);
            o1.x = fmaxf(acc[mf][nf][2] + bv.x, 0.f);
            o1.y = fmaxf(acc[mf][nf][3] + bv.y, 0.f);
            *(float2*)&g_C1[(size_t)gm0*NS + gn]       = o0;
            *(float2*)&g_C1[(size_t)(gm0+8)*NS + gn]   = o1;
        }
    }
}

__global__ __launch_bounds__(256) void gemm2_kernel(
    const float* __restrict__ W,     // [ND][NS]
    const float* __restrict__ bias)  // [ND]
{
    __shared__ __align__(16) uint32_t As[128][36];
    __shared__ __align__(16) uint32_t Bs[128][36];

    const int tid  = threadIdx.x;
    const int warp = tid >> 5;
    const int lane = tid & 31;
    const int m0c  = blockIdx.y * 128;
    const int n0c  = blockIdx.x * 128;

    const int row = tid >> 1;
    const int kq  = tid & 1;

    const float* arow = g_C1 + (size_t)(m0c + row) * NS;
    const float* brow = W    + (size_t)(n0c + row) * NS;

    const int wm = (warp & 1) * 64;
    const int wn = (warp >> 1) * 32;
    const int ly = lane >> 2;
    const int lx = lane & 3;

    float acc[4][4][4] = {};

    float4 pa[4], pb[4];
#pragma unroll
    for (int q = 0; q < 4; q++) {
        pa[q] = *(const float4*)&arow[kq*16 + q*4];
        pb[q] = *(const float4*)&brow[kq*16 + q*4];
    }

    for (int k0 = 0; k0 < NS; k0 += 32) {
#pragma unroll
        for (int q = 0; q < 4; q++) {
            const int c = kq*16 + q*4;
            *(uint4*)&As[row][c] = make_uint4(f2tf(pa[q].x), f2tf(pa[q].y), f2tf(pa[q].z), f2tf(pa[q].w));
            *(uint4*)&Bs[row][c] = make_uint4(f2tf(pb[q].x), f2tf(pb[q].y), f2tf(pb[q].z), f2tf(pb[q].w));
        }
        __syncthreads();
        if (k0 + 32 < NS) {
#pragma unroll
            for (int q = 0; q < 4; q++) {
                pa[q] = *(const float4*)&arow[k0+32 + kq*16 + q*4];
                pb[q] = *(const float4*)&brow[k0+32 + kq*16 + q*4];
            }
        }
#pragma unroll
        for (int kk = 0; kk < 4; kk++) {
            const int kb = kk * 8;
            uint32_t af[4][4], bf[4][2];
#pragma unroll
            for (int mf = 0; mf < 4; mf++) {
                const int rb = wm + mf*16 + ly;
                af[mf][0] = As[rb    ][kb + lx];
                af[mf][1] = As[rb + 8][kb + lx];
                af[mf][2] = As[rb    ][kb + lx + 4];
                af[mf][3] = As[rb + 8][kb + lx + 4];
            }
#pragma unroll
            for (int nf = 0; nf < 4; nf++) {
                const int nb = wn + nf*8 + ly;
                bf[nf][0] = Bs[nb][kb + lx];
                bf[nf][1] = Bs[nb][kb + lx + 4];
            }
#pragma unroll
            for (int mf = 0; mf < 4; mf++)
#pragma unroll
                for (int nf = 0; nf < 4; nf++)
                    mma_tf32(acc[mf][nf], af[mf], bf[nf]);
        }
        __syncthreads();
    }

#pragma unroll
    for (int nf = 0; nf < 4; nf++) {
        const int gn = n0c + wn + nf*8 + lx*2;
        const float2 bv = *(const float2*)&bias[gn];
#pragma unroll
        for (int mf = 0; mf < 4; mf++) {
            const int gm0 = m0c + wm + mf*16 + ly;
            float2 o0, o1;
            o0.x = fmaxf(acc[mf][nf][0] + bv.x, 0.f);
            o0.y = fmaxf(acc[mf][nf][1] + bv.y, 0.f);
            o1.x = fmaxf(acc[mf][nf][2] + bv.x, 0.f);
            o1.y = fmaxf(acc[mf][nf][3] + bv.y, 0.f);
            *(float2*)&g_L[(size_t)gm0*ND + gn]       = o0;
            *(float2*)&g_L[(size_t)(gm0+8)*ND + gn]   = o1;
        }
    }
}

// ---------------------------------------------------------------------------
// Barrier flag reset (graph replays reuse state)
// ---------------------------------------------------------------------------
__global__ void init_bar_kernel()
{
    if (threadIdx.x < 8) g_flag[threadIdx.x] = 0u;
}

// ---------------------------------------------------------------------------
// Persistent recurrent kernel, bf16x2 split-precision mma + ldmatrix.
// 128 CTAs = 8 m-blocks x 16 n-blocks; CTA tile 32(M) x 32(N), K=512.
// 256 threads = 8 warps in 2(M) x 4(N); warp tile 16m x 8n.
// Inner loop per k32: 6 ldmatrix.x4 + 6 mma (main + 2 residual terms).
// L(t+1) prefetched before the inter-step barrier to hide L2 latency.
// ---------------------------------------------------------------------------
__global__ __launch_bounds__(256, 1) void step_persist(
    const float* __restrict__ Wh,     // [ND][ND]
    const float* __restrict__ bhid)   // [ND]
{
    extern __shared__ uint32_t smu[]; // bf16 PAIRS, row stride PROW
    uint32_t* Ws0 = smu;              // [32][PROW] W main
    uint32_t* Ws1 = smu + 32*PROW;    // [32][PROW] W residual
    uint32_t* hs0 = smu + 64*PROW;    // [32][PROW] h main
    uint32_t* hs1 = smu + 96*PROW;    // [32][PROW] h residual

    const int tid  = threadIdx.x;
    const int bx   = blockIdx.x;
    const int mb   = bx >> 4;          // 0..7
    const int m0   = mb * 32;
    const int n0   = (bx & 15) * 32;
    const int warp = tid >> 5;
    const int lane = tid & 31;
    const int wm   = (warp & 1) * 16;
    const int wn   = (warp >> 1) * 8;
    const int ly   = lane >> 2;
    const int lx   = lane & 3;

    // --- split W slice into bf16 hi/lo pairs in smem (once) ---
#pragma unroll
    for (int i = 0; i < 32; i++) {
        const int idx = tid + i*256;        // 0..8191 pair slots (32 rows x 256)
        const int r   = idx >> 8;
        const int p   = idx & 255;          // pair col (2 k values)
        float2 w = *(const float2*)&Wh[(size_t)(n0+r)*ND + p*2];
        __nv_bfloat16 h0x = __float2bfloat16_rn(w.x);
        __nv_bfloat16 h0y = __float2bfloat16_rn(w.y);
        float rx = w.x - __bfloat162float(h0x);
        float ry = w.y - __bfloat162float(h0y);
        __nv_bfloat162 p0; p0.x = h0x; p0.y = h0y;
        __nv_bfloat162 p1; p1.x = __float2bfloat16_rn(rx); p1.y = __float2bfloat16_rn(ry);
        Ws0[r*PROW + p] = *(uint32_t*)&p0;
        Ws1[r*PROW + p] = *(uint32_t*)&p1;
    }
    const int gnc = n0 + wn + lx*2;
    const float bb0 = bhid[gnc];
    const float bb1 = bhid[gnc + 1];
    const int gm0 = m0 + wm + ly;          // epilogue rows gm0, gm0+8

    // per-lane ldmatrix base addresses (bytes, shared space)
    // A x4 (m16 x k16): lanes 0-15 -> rows wm+(lane&15) @ k+0..7 ; lanes 16-31 -> same rows @ k+8..15
    const uint32_t aOff = (uint32_t)((wm + (lane & 15)) * PROW * 4 + (lane >> 4) * 16);
    const uint32_t aHi  = smem_u32(hs0) + aOff;
    const uint32_t aLo  = smem_u32(hs1) + aOff;
    // B x4 (n8 x k32): lanes (lane&7) -> rows wn+(lane&7) @ k + (lane>>3)*8
    const uint32_t bOff = (uint32_t)((wn + (lane & 7)) * PROW * 4 + (lane >> 3) * 16);
    const uint32_t bHi  = smem_u32(Ws0) + bOff;
    const uint32_t bLo  = smem_u32(Ws1) + bOff;

    __syncthreads();

    // prefetch L for t=0
    float2 l0 = __ldg((const float2*)&g_L[(size_t)gm0*ND + gnc]);
    float2 l1 = __ldg((const float2*)&g_L[(size_t)(gm0+8)*ND + gnc]);

    for (int t = 0; t < NT; t++) {
        __nv_bfloat16* __restrict__ ho0 = g_h0[(t+1) & 1];
        __nv_bfloat16* __restrict__ ho1 = g_h1[(t+1) & 1];

        float acc[4] = {0.f, 0.f, 0.f, 0.f};
        float cor[4] = {0.f, 0.f, 0.f, 0.f};
        if (t > 0) {
            const __nv_bfloat16* __restrict__ hi0 = g_h0[t & 1];
            const __nv_bfloat16* __restrict__ hi1 = g_h1[t & 1];
            // stage h tiles (bypass L1: written by peer SMs last step)
#pragma unroll
            for (int i = 0; i < 8; i++) {
                const int idx = tid + i*256;
                const int r   = idx >> 6;
                const int c4  = idx & 63;
                uint4 v = __ldcg((const uint4*)(hi0 + (size_t)(m0+r)*ND) + c4);
                *(uint4*)&hs0[r*PROW + c4*4] = v;
            }
#pragma unroll
            for (int i = 0; i < 8; i++) {
                const int idx = tid + i*256;
                const int r   = idx >> 6;
                const int c4  = idx & 63;
                uint4 v = __ldcg((const uint4*)(hi1 + (size_t)(m0+r)*ND) + c4);
                *(uint4*)&hs1[r*PROW + c4*4] = v;
            }
            __syncthreads();

#pragma unroll 4
            for (int kc = 0; kc < 16; kc++) {  // k32 chunks
                const uint32_t off = kc * 64;  // 32 bf16 = 64 bytes
                uint32_t ah0[4], ah1[4], al0[4], al1[4], bh[4], bl[4];
                ldsm_x4(ah0, aHi + off);
                ldsm_x4(ah1, aHi + off + 32);
                ldsm_x4(al0, aLo + off);
                ldsm_x4(al1, aLo + off + 32);
                ldsm_x4(bh,  bHi + off);
                ldsm_x4(bl,  bLo + off);
                mma_bf16(acc, ah0, &bh[0]);    // main, chunk 0
                mma_bf16(cor, al0, &bh[0]);    // h residual
                mma_bf16(cor, ah0, &bl[0]);    // W residual
                mma_bf16(acc, ah1, &bh[2]);    // main, chunk 1
                mma_bf16(cor, al1, &bh[2]);
                mma_bf16(cor, ah1, &bl[2]);
            }
        }

        // epilogue: +corr +L +bias, tanh, split to bf16 pair, store
        {
            float o00 = tanhf(acc[0] + cor[0] + l0.x + bb0);
            float o01 = tanhf(acc[1] + cor[1] + l0.y + bb1);
            float o10 = tanhf(acc[2] + cor[2] + l1.x + bb0);
            float o11 = tanhf(acc[3] + cor[3] + l1.y + bb1);

            __nv_bfloat162 h00, h01, r00, r01;
            h00.x = __float2bfloat16_rn(o00);
            h00.y = __float2bfloat16_rn(o01);
            r00.x = __float2bfloat16_rn(o00 - __bfloat162float(h00.x));
            r00.y = __float2bfloat16_rn(o01 - __bfloat162float(h00.y));
            h01.x = __float2bfloat16_rn(o10);
            h01.y = __float2bfloat16_rn(o11);
            r01.x = __float2bfloat16_rn(o10 - __bfloat162float(h01.x));
            r01.y = __float2bfloat16_rn(o11 - __bfloat162float(h01.y));

            *(uint32_t*)&ho0[(size_t)gm0*ND + gnc]     = *(uint32_t*)&h00;
            *(uint32_t*)&ho1[(size_t)gm0*ND + gnc]     = *(uint32_t*)&r00;
            *(uint32_t*)&ho0[(size_t)(gm0+8)*ND + gnc] = *(uint32_t*)&h01;
            *(uint32_t*)&ho1[(size_t)(gm0+8)*ND + gnc] = *(uint32_t*)&r01;
        }

        // prefetch L for t+1 BEFORE the barrier (hides L2 latency under poll)
        if (t + 1 < NT) {
            const float* __restrict__ Ln = g_L + (size_t)(t+1) * NB * ND;
            l0 = __ldg((const float2*)&Ln[(size_t)gm0*ND + gnc]);
            l1 = __ldg((const float2*)&Ln[(size_t)(gm0+8)*ND + gnc]);
        }

        // per-m-block barrier (16 CTAs); also guards hs WAR for next step
        __threadfence();
        __syncthreads();
        if (tid == 0) {
            const unsigned target = (unsigned)(t + 1) * 16u;
            atomicAdd(&g_flag[mb], 1u);
            while (*((volatile unsigned*)&g_flag[mb]) < target) { }
        }
        __syncthreads();
    }
}

// ---------------------------------------------------------------------------
// Row L2-normalize final h (split arrays, index 0 after even NT)
// ---------------------------------------------------------------------------
__global__ __launch_bounds__(128) void norm_kernel(float* __restrict__ out)
{
    __shared__ float red[4];
    const int row = blockIdx.x;
    const int tid = threadIdx.x;   // each covers 4 cols

    const __nv_bfloat162* h0 = (const __nv_bfloat162*)(g_h0[0] + (size_t)row * ND);
    const __nv_bfloat162* h1 = (const __nv_bfloat162*)(g_h1[0] + (size_t)row * ND);
    __nv_bfloat162 a0 = h0[tid*2], a1 = h0[tid*2+1];
    __nv_bfloat162 b0 = h1[tid*2], b1 = h1[tid*2+1];
    float4 v;
    v.x = __bfloat162float(a0.x) + __bfloat162float(b0.x);
    v.y = __bfloat162float(a0.y) + __bfloat162float(b0.y);
    v.z = __bfloat162float(a1.x) + __bfloat162float(b1.x);
    v.w = __bfloat162float(a1.y) + __bfloat162float(b1.y);

    float s = v.x*v.x + v.y*v.y + v.z*v.z + v.w*v.w;
#pragma unroll
    for (int o = 16; o; o >>= 1) s += __shfl_xor_sync(0xFFFFFFFFu, s, o);
    if ((tid & 31) == 0) red[tid >> 5] = s;
    __syncthreads();
    const float tot = red[0] + red[1] + red[2] + red[3];
    const float inv = 1.f / fmaxf(sqrtf(tot), 1e-12f);
    float4 o4 = make_float4(v.x*inv, v.y*inv, v.z*inv, v.w*inv);
    *(float4*)&out[(size_t)row * ND + tid * 4] = o4;
}

// ---------------------------------------------------------------------------
// Launch
// ---------------------------------------------------------------------------
extern "C" void kernel_launch(void* const* d_in, const int* in_sizes, int n_in,
                              void* d_out, int out_size)
{
    const int*   x     = (const int*)  d_in[0];
    const float* emb   = (const float*)d_in[1];
    const float* W_inp = (const float*)d_in[2];
    const float* b_inp = (const float*)d_in[3];
    const float* W_mid = (const float*)d_in[4];
    const float* b_mid = (const float*)d_in[5];
    const float* W_hid = (const float*)d_in[6];
    const float* b_hid = (const float*)d_in[7];
    float* out = (float*)d_out;

    cudaFuncSetAttribute(step_persist, cudaFuncAttributeMaxDynamicSharedMemorySize, STEP_SMEM);

    // Feed-forward part for ALL timesteps (tensor cores, tf32)
    gemm1_kernel<<<dim3(NS/128, NM/128), 256>>>(x, emb, W_inp, b_inp);
    gemm2_kernel<<<dim3(ND/128, NM/128), 256>>>(W_mid, b_mid);

    // Recurrence: persistent kernel, per-m-block barriers, bf16x2 mma + ldmatrix
    init_bar_kernel<<<1, 32>>>();
    step_persist<<<SGRID, 256, STEP_SMEM>>>(W_hid, b_hid);

    norm_kernel<<<NB, 128>>>(out);
}